// round 14
// baseline (speedup 1.0000x reference)
#include <cuda_runtime.h>
#include <cstdint>

// ============================================================================
// GeneralRNN: h_t = hmlp([h_{t-1}, x_t]); y_t = ymlp(h_t)
// B=256, S=1024, D_IN=64, H=256, W_H=512, W_Y=256, D_OUT=64 (fp32).
//
// Persistent kernel, no inter-CTA sync (recurrence is per-batch-row
// independent). R13 change vs R12: M=4 rows/CTA -> M=2 rows/CTA, grid 64 ->
// 128 CTAs. R12's ncu showed active-SM issue ~67% with only 64/148 SMs
// populated: the kernel was issue-bound on too few SMs. Doubling the grid
// doubles chip issue capacity and halves per-thread work; L2 weight traffic
// doubles to ~201 MB/step but stays under the LTS cap (weights are
// L2-resident). Inner products keep the R12 structure: fma.rn.f32x2 with
// duplicated-pair activations in smem (LDS.128 covers two k's) and a 2x16
// register double buffer hiding L2 latency on the weight stream.
// ============================================================================

#define ULL unsigned long long

static constexpr int B    = 256;
static constexpr int S    = 1024;
static constexpr int DIN  = 64;
static constexpr int H    = 256;
static constexpr int WH   = 512;
static constexpr int WY   = 256;
static constexpr int DOUT = 64;
static constexpr int KHX  = H + DIN;   // 320

static constexpr int M    = 2;         // batch rows per CTA
static constexpr int NCTA = B / M;     // 128
static constexpr int T    = 256;       // threads per CTA

// ---- packed f32x2 helpers (sm_100+) ----------------------------------------
__device__ __forceinline__ void ffma2(ULL& c, ULL a, ULL b) {
    asm("fma.rn.f32x2 %0, %1, %2, %0;" : "+l"(c) : "l"(a), "l"(b));
}
__device__ __forceinline__ ULL fadd2(ULL a, ULL b) {
    ULL r; asm("add.rn.f32x2 %0, %1, %2;" : "=l"(r) : "l"(a), "l"(b)); return r;
}
__device__ __forceinline__ ULL pack2(float lo, float hi) {
    ULL r;
    asm("mov.b64 %0, {%1, %2};"
        : "=l"(r) : "r"(__float_as_uint(lo)), "r"(__float_as_uint(hi)));
    return r;
}
__device__ __forceinline__ void unpack2(ULL v, float& lo, float& hi) {
    unsigned int a, b;
    asm("mov.b64 {%0, %1}, %2;" : "=r"(a), "=r"(b) : "l"(v));
    lo = __uint_as_float(a); hi = __uint_as_float(b);
}
__device__ __forceinline__ float silu_f(float z) {
    return z / (1.0f + __expf(-z));
}
__device__ __forceinline__ ULL ldgw(const float* p) {   // 64-bit weight load
    return __ldg(reinterpret_cast<const ULL*>(p));
}

// ----------------------------------------------------------------------------
// Pipelined dot product over KLEN weight rows for M batch rows.
//   acc[m] += sum_k act[m*ASTRIDE + k] (packed dup) * W cols (wp + k*WSTRIDE)
// Register double buffer: while one 16-entry buffer is consumed, the other's
// loads are in flight. KLEN must be a multiple of 32. act must be 16B aligned
// (LDS.128 broadcast reads two consecutive k's at once).
// ----------------------------------------------------------------------------
template<int KLEN, int WSTRIDE, int ASTRIDE>
__device__ __forceinline__ void dotp(ULL acc[M],
                                     const float* __restrict__ wp,
                                     const ULL* __restrict__ act)
{
    constexpr int U = 16;
    static_assert(KLEN % (2 * U) == 0, "KLEN must be multiple of 32");
    ULL wa[U], wb[U];

    #pragma unroll
    for (int u = 0; u < U; ++u) wa[u] = ldgw(wp + (size_t)u * WSTRIDE);

    #pragma unroll 1
    for (int k0 = 0; k0 < KLEN; k0 += 2 * U) {
        // prefetch buffer B (k0+U .. k0+2U-1) — always in range
        #pragma unroll
        for (int u = 0; u < U; ++u)
            wb[u] = ldgw(wp + (size_t)(k0 + U + u) * WSTRIDE);

        // consume buffer A
        #pragma unroll
        for (int u = 0; u < U; u += 2) {
            #pragma unroll
            for (int m = 0; m < M; ++m) {
                const ulonglong2 hv =
                    *reinterpret_cast<const ulonglong2*>(act + m * ASTRIDE + k0 + u);
                ffma2(acc[m], hv.x, wa[u]);
                ffma2(acc[m], hv.y, wa[u + 1]);
            }
        }

        // prefetch buffer A for next iteration (guarded at the tail)
        #pragma unroll
        for (int u = 0; u < U; ++u) {
            const int kk = k0 + 2 * U + u;
            if (kk < KLEN) wa[u] = ldgw(wp + (size_t)kk * WSTRIDE);
        }

        // consume buffer B
        #pragma unroll
        for (int u = 0; u < U; u += 2) {
            #pragma unroll
            for (int m = 0; m < M; ++m) {
                const ulonglong2 hv =
                    *reinterpret_cast<const ulonglong2*>(act + m * ASTRIDE + k0 + U + u);
                ffma2(acc[m], hv.x, wb[u]);
                ffma2(acc[m], hv.y, wb[u + 1]);
            }
        }
    }
}

__global__ __launch_bounds__(T, 1)
void rnn_persistent_kernel(
    const float* __restrict__ x,    // [B, S, DIN]
    const float* __restrict__ W1h,  // [KHX, WH]
    const float* __restrict__ b1h,  // [WH]
    const float* __restrict__ W2h,  // [WH, H]
    const float* __restrict__ b2h,  // [H]
    const float* __restrict__ W1y,  // [H, WY]
    const float* __restrict__ b1y,  // [WY]
    const float* __restrict__ W2y,  // [WY, DOUT]
    const float* __restrict__ b2y,  // [DOUT]
    float* __restrict__ outs,       // [B, S, DOUT]
    float* __restrict__ hid)        // [S+1, B, H]
{
    // Activation buffers hold duplicated packed pairs (v,v): one LDS broadcast
    // feeds fma.rn.f32x2 directly. 16B aligned for LDS.128 paired-k reads.
    __shared__ __align__(16) ULL hx2[M][KHX];        // [h | x_t]
    __shared__ __align__(16) ULL a2 [M][WH];         // silu(hmlp layer 1)
    __shared__ __align__(16) ULL yh2[M][WY];         // silu(ymlp layer 1)
    __shared__ __align__(16) ULL red [M][H / 2];     // split-K reduction (ph 2,3)
    __shared__ __align__(16) ULL red4[8][M][DOUT/2]; // split-K reduction (ph 4)

    const int tid = threadIdx.x;
    const int b0  = blockIdx.x * M;

    // h0 = 0; hiddens[0] = 0
    for (int i = tid; i < M * H; i += T) {
        const int m = i / H, j = i % H;
        hx2[m][j] = 0ULL;
        hid[(size_t)(b0 + m) * H + j] = 0.0f;
    }
    __syncthreads();

    for (int t = 0; t < S; ++t) {
        // ---- load x_t into hx columns [H, H+DIN) --------------------------
        if (tid < M * DIN) {                          // 2 x 64 = 128 threads
            const int m = tid >> 6, d = tid & 63;
            const float xv = x[((size_t)(b0 + m) * S + t) * DIN + d];
            hx2[m][H + d] = pack2(xv, xv);
        }
        __syncthreads();

        // ---- phase 1: a = silu(hx @ W1h + b1h)  (K=320, N=512) ------------
        {
            const int j2 = 2 * tid;
            ULL acc[M];
            const ULL bias = *(const ULL*)(b1h + j2);
            #pragma unroll
            for (int m = 0; m < M; ++m) acc[m] = bias;

            dotp<KHX, WH, KHX>(acc, W1h + j2, &hx2[0][0]);

            #pragma unroll
            for (int m = 0; m < M; ++m) {
                float z0, z1; unpack2(acc[m], z0, z1);
                const float s0 = silu_f(z0), s1 = silu_f(z1);
                a2[m][j2]     = pack2(s0, s0);
                a2[m][j2 + 1] = pack2(s1, s1);
            }
        }
        __syncthreads();

        // ---- phase 2: h' = a @ W2h + b2h  (K=512 split 2-way, N=256) ------
        {
            const int jj = tid & 127, half = tid >> 7;
            const int j2 = 2 * jj;
            ULL acc[M];
            if (half == 0) {
                const ULL bias = *(const ULL*)(b2h + j2);
                #pragma unroll
                for (int m = 0; m < M; ++m) acc[m] = bias;
            } else {
                #pragma unroll
                for (int m = 0; m < M; ++m) acc[m] = 0ULL;
            }
            dotp<256, H, WH>(acc, W2h + (size_t)(half * 256) * H + j2,
                             &a2[0][0] + half * 256);

            if (half == 1) {
                #pragma unroll
                for (int m = 0; m < M; ++m) red[m][jj] = acc[m];
            }
            __syncthreads();
            if (half == 0) {
                #pragma unroll
                for (int m = 0; m < M; ++m) {
                    const ULL v = fadd2(acc[m], red[m][jj]);
                    float h0f, h1f; unpack2(v, h0f, h1f);
                    *(float2*)(hid + ((size_t)(t + 1) * B + (b0 + m)) * H + j2)
                        = make_float2(h0f, h1f);
                    hx2[m][j2]     = pack2(h0f, h0f);
                    hx2[m][j2 + 1] = pack2(h1f, h1f);
                }
            }
        }
        __syncthreads();

        // ---- phase 3: yh = silu(h' @ W1y + b1y)  (K=256 split 2-way) ------
        {
            const int jj = tid & 127, half = tid >> 7;
            const int j2 = 2 * jj;
            ULL acc[M];
            if (half == 0) {
                const ULL bias = *(const ULL*)(b1y + j2);
                #pragma unroll
                for (int m = 0; m < M; ++m) acc[m] = bias;
            } else {
                #pragma unroll
                for (int m = 0; m < M; ++m) acc[m] = 0ULL;
            }
            dotp<128, WY, KHX>(acc, W1y + (size_t)(half * 128) * WY + j2,
                               &hx2[0][0] + half * 128);

            if (half == 1) {
                #pragma unroll
                for (int m = 0; m < M; ++m) red[m][jj] = acc[m];
            }
            __syncthreads();
            if (half == 0) {
                #pragma unroll
                for (int m = 0; m < M; ++m) {
                    const ULL v = fadd2(acc[m], red[m][jj]);
                    float z0, z1; unpack2(v, z0, z1);
                    const float s0 = silu_f(z0), s1 = silu_f(z1);
                    yh2[m][j2]     = pack2(s0, s0);
                    yh2[m][j2 + 1] = pack2(s1, s1);
                }
            }
        }
        __syncthreads();

        // ---- phase 4: y = yh @ W2y + b2y  (K=256 split 8-way, N=64) -------
        {
            const int cp = tid & 31, oct = tid >> 5;
            const int j2 = 2 * cp;
            ULL acc[M];
            #pragma unroll
            for (int m = 0; m < M; ++m) acc[m] = 0ULL;

            dotp<32, DOUT, WY>(acc, W2y + (size_t)(oct * 32) * DOUT + j2,
                               &yh2[0][0] + oct * 32);

            #pragma unroll
            for (int m = 0; m < M; ++m) red4[oct][m][cp] = acc[m];
            __syncthreads();
            if (oct == 0) {
                #pragma unroll
                for (int m = 0; m < M; ++m) {
                    ULL v = acc[m];
                    #pragma unroll
                    for (int o = 1; o < 8; ++o) v = fadd2(v, red4[o][m][cp]);
                    v = fadd2(v, *(const ULL*)(b2y + j2));
                    float y0, y1; unpack2(v, y0, y1);
                    *(float2*)(outs + ((size_t)(b0 + m) * S + t) * DOUT + j2)
                        = make_float2(y0, y1);
                }
            }
        }
        __syncthreads();   // guard smem buffer reuse across iterations
    }
}

extern "C" void kernel_launch(void* const* d_in, const int* in_sizes, int n_in,
                              void* d_out, int out_size) {
    (void)in_sizes; (void)n_in; (void)out_size;
    const float* x   = (const float*)d_in[0];
    const float* W1h = (const float*)d_in[1];
    const float* b1h = (const float*)d_in[2];
    const float* W2h = (const float*)d_in[3];
    const float* b2h = (const float*)d_in[4];
    const float* W1y = (const float*)d_in[5];
    const float* b1y = (const float*)d_in[6];
    const float* W2y = (const float*)d_in[7];
    const float* b2y = (const float*)d_in[8];

    float* outs = (float*)d_out;                       // [B, S, DOUT]
    float* hid  = outs + (size_t)B * S * DOUT;         // [S+1, B, H]

    rnn_persistent_kernel<<<NCTA, T>>>(x, W1h, b1h, W2h, b2h,
                                       W1y, b1y, W2y, b2y, outs, hid);
}

// round 15
// speedup vs baseline: 1.8198x; 1.8198x over previous
#include <cuda_runtime.h>
#include <cstdint>

// ============================================================================
// GeneralRNN: h_t = hmlp([h_{t-1}, x_t]); y_t = ymlp(h_t)
// B=256, S=1024, D_IN=64, H=256, W_H=512, W_Y=256, D_OUT=64 (fp32).
//
// R14 design:
//  * Recurrent part (hmlp only): 64 persistent CTAs x 4 batch rows, 4 output
//    cols/thread (LDG.128 weights) + split-K — halves LDS wavefronts vs R12.
//    Streams W1h+W2h (1.18 MB) from L2 per step.
//  * ymlp has NO recurrence: computed by 8192 extra CTAs of the SAME launch
//    (32 rows x full ymlp each) running on the ~84 SMs the recurrence doesn't
//    use. They consume hid as it is produced, gated by per-recurrent-CTA
//    progress counters (release store / acquire poll). A tiny init kernel
//    resets the counters so every graph replay is self-contained.
// ============================================================================

#define ULL unsigned long long

static constexpr int B    = 256;
static constexpr int S    = 1024;
static constexpr int DIN  = 64;
static constexpr int H    = 256;
static constexpr int WH   = 512;
static constexpr int WY   = 256;
static constexpr int DOUT = 64;
static constexpr int KHX  = H + DIN;       // 320

static constexpr int M        = 4;         // batch rows per recurrent CTA
static constexpr int REC_CTAS = B / M;     // 64
static constexpr int T        = 256;
static constexpr int YROWS    = 32;        // rows per y-tile CTA
static constexpr int YTILES   = S * (B / YROWS);   // 8192
static constexpr int GRID     = REC_CTAS + YTILES;

// dyn smem layout in ULL units ------------------------------------------------
static constexpr int HX_OFF   = 0;                     // [M][KHX]      1280
static constexpr int A2_OFF   = HX_OFF + M * KHX;      // [M][WH]       2048
static constexpr int REDA_OFF = A2_OFF + M * WH;       // [M][128][2]   1024
static constexpr int REDB_OFF = REDA_OFF + M * 128 * 2;// [3][M][64][2] 1536
// y-branch union: hs [32][256] at 0, us [32][256] at 8192
static constexpr int US_OFF   = YROWS * H;             // 8192
static constexpr int DSMEM_ULL = 2 * YROWS * H;        // 16384 ULL = 128 KB
static constexpr int DSMEM_BYTES = DSMEM_ULL * 8;

__device__ unsigned g_progress[REC_CTAS];

// ---- packed f32x2 helpers (sm_100+) ----------------------------------------
__device__ __forceinline__ void ffma2(ULL& c, ULL a, ULL b) {
    asm("fma.rn.f32x2 %0, %1, %2, %0;" : "+l"(c) : "l"(a), "l"(b));
}
__device__ __forceinline__ ULL fadd2(ULL a, ULL b) {
    ULL r; asm("add.rn.f32x2 %0, %1, %2;" : "=l"(r) : "l"(a), "l"(b)); return r;
}
__device__ __forceinline__ ULL pack2(float lo, float hi) {
    ULL r;
    asm("mov.b64 %0, {%1, %2};"
        : "=l"(r) : "r"(__float_as_uint(lo)), "r"(__float_as_uint(hi)));
    return r;
}
__device__ __forceinline__ void unpack2(ULL v, float& lo, float& hi) {
    unsigned int a, b;
    asm("mov.b64 {%0, %1}, %2;" : "=r"(a), "=r"(b) : "l"(v));
    lo = __uint_as_float(a); hi = __uint_as_float(b);
}
__device__ __forceinline__ float silu_f(float z) {
    return z / (1.0f + __expf(-z));
}
__device__ __forceinline__ ULL ldgw(const float* p) {       // 64-bit weight load
    return __ldg(reinterpret_cast<const ULL*>(p));
}
__device__ __forceinline__ ulonglong2 ldgw4(const float* p) { // 128-bit weight load
    return __ldg(reinterpret_cast<const ulonglong2*>(p));
}
__device__ __forceinline__ void rel_store(unsigned* p, unsigned v) {
    asm volatile("st.release.gpu.b32 [%0], %1;" :: "l"(p), "r"(v) : "memory");
}
__device__ __forceinline__ unsigned acq_load(const unsigned* p) {
    unsigned v;
    asm volatile("ld.acquire.gpu.b32 %0, [%1];" : "=r"(v) : "l"(p) : "memory");
    return v;
}

// ----------------------------------------------------------------------------
// Recurrent dot: 4 output cols per thread, M batch rows, double-buffered
// LDG.128 weight stream. acc[m][0] = cols (j4,j4+1), acc[m][1] = (j4+2,j4+3).
// KLEN must be a multiple of 16. act: dup-packed, element stride AS per row m.
// ----------------------------------------------------------------------------
template<int KLEN, int WS, int AS>
__device__ __forceinline__ void dotp4(ULL acc[M][2],
                                      const float* __restrict__ wp,
                                      const ULL* __restrict__ act)
{
    constexpr int U = 8;
    static_assert(KLEN % (2 * U) == 0, "KLEN % 16");
    ulonglong2 wa[U], wb[U];

    #pragma unroll
    for (int u = 0; u < U; ++u) wa[u] = ldgw4(wp + (size_t)u * WS);

    #pragma unroll 1
    for (int k0 = 0; k0 < KLEN; k0 += 2 * U) {
        #pragma unroll
        for (int u = 0; u < U; ++u)
            wb[u] = ldgw4(wp + (size_t)(k0 + U + u) * WS);

        #pragma unroll
        for (int u = 0; u < U; u += 2) {
            #pragma unroll
            for (int m = 0; m < M; ++m) {
                const ulonglong2 hv =
                    *reinterpret_cast<const ulonglong2*>(act + m * AS + k0 + u);
                ffma2(acc[m][0], hv.x, wa[u].x);
                ffma2(acc[m][1], hv.x, wa[u].y);
                ffma2(acc[m][0], hv.y, wa[u + 1].x);
                ffma2(acc[m][1], hv.y, wa[u + 1].y);
            }
        }
        #pragma unroll
        for (int u = 0; u < U; ++u) {
            const int kk = k0 + 2 * U + u;
            if (kk < KLEN) wa[u] = ldgw4(wp + (size_t)kk * WS);
        }
        #pragma unroll
        for (int u = 0; u < U; u += 2) {
            #pragma unroll
            for (int m = 0; m < M; ++m) {
                const ulonglong2 hv =
                    *reinterpret_cast<const ulonglong2*>(act + m * AS + k0 + U + u);
                ffma2(acc[m][0], hv.x, wb[u].x);
                ffma2(acc[m][1], hv.x, wb[u].y);
                ffma2(acc[m][0], hv.y, wb[u + 1].x);
                ffma2(acc[m][1], hv.y, wb[u + 1].y);
            }
        }
    }
}

// ----------------------------------------------------------------------------
// y-branch dot: R rows x 2 cols per thread over K=256, LDG.64 weight stream.
// ----------------------------------------------------------------------------
template<int R, int WS>
__device__ __forceinline__ void ydot(ULL acc[R],
                                     const float* __restrict__ wp,
                                     const ULL* __restrict__ act)  // row stride H
{
    constexpr int U = 16;
    ULL wa[U], wb[U];
    #pragma unroll
    for (int u = 0; u < U; ++u) wa[u] = ldgw(wp + (size_t)u * WS);

    #pragma unroll 1
    for (int k0 = 0; k0 < 256; k0 += 2 * U) {
        #pragma unroll
        for (int u = 0; u < U; ++u)
            wb[u] = ldgw(wp + (size_t)(k0 + U + u) * WS);
        #pragma unroll
        for (int u = 0; u < U; u += 2) {
            #pragma unroll
            for (int r = 0; r < R; ++r) {
                const ulonglong2 hv =
                    *reinterpret_cast<const ulonglong2*>(act + r * H + k0 + u);
                ffma2(acc[r], hv.x, wa[u]);
                ffma2(acc[r], hv.y, wa[u + 1]);
            }
        }
        #pragma unroll
        for (int u = 0; u < U; ++u) {
            const int kk = k0 + 2 * U + u;
            if (kk < 256) wa[u] = ldgw(wp + (size_t)kk * WS);
        }
        #pragma unroll
        for (int u = 0; u < U; u += 2) {
            #pragma unroll
            for (int r = 0; r < R; ++r) {
                const ulonglong2 hv =
                    *reinterpret_cast<const ulonglong2*>(act + r * H + k0 + U + u);
                ffma2(acc[r], hv.x, wb[u]);
                ffma2(acc[r], hv.y, wb[u + 1]);
            }
        }
    }
}

__global__ void init_progress_kernel() {
    if (threadIdx.x < REC_CTAS) g_progress[threadIdx.x] = 0u;
}

__global__ __launch_bounds__(T, 1)
void rnn_fused_kernel(
    const float* __restrict__ x,    // [B, S, DIN]
    const float* __restrict__ W1h,  // [KHX, WH]
    const float* __restrict__ b1h,
    const float* __restrict__ W2h,  // [WH, H]
    const float* __restrict__ b2h,
    const float* __restrict__ W1y,  // [H, WY]
    const float* __restrict__ b1y,
    const float* __restrict__ W2y,  // [WY, DOUT]
    const float* __restrict__ b2y,
    float* __restrict__ outs,       // [B, S, DOUT]
    float* __restrict__ hid)        // [S+1, B, H]
{
    extern __shared__ __align__(16) ULL sm[];
    const int tid = threadIdx.x;
    const int bid = blockIdx.x;

    if (bid < REC_CTAS) {
        // ====================== recurrent branch (hmlp) =====================
        ULL* hx  = sm + HX_OFF;     // [M][KHX] dup-packed
        ULL* a2  = sm + A2_OFF;     // [M][WH]  dup-packed
        ULL* rdA = sm + REDA_OFF;   // [M][128][2]
        ULL* rdB = sm + REDB_OFF;   // [3][M][64][2]
        const int b0 = bid * M;

        for (int i = tid; i < M * H; i += T) {
            const int m = i / H, j = i % H;
            hx[m * KHX + j] = 0ULL;
            hid[(size_t)(b0 + m) * H + j] = 0.0f;   // hiddens[0] = 0
        }
        __syncthreads();

        for (int t = 0; t < S; ++t) {
            // x_t into hx cols [H, H+DIN)
            {
                const int m = tid >> 6, d = tid & 63;
                const float xv = x[((size_t)(b0 + m) * S + t) * DIN + d];
                hx[m * KHX + H + d] = pack2(xv, xv);
            }
            __syncthreads();

            // phase 1: a = silu(hx @ W1h + b1h). 4 cols/thread, split-K 2-way.
            {
                const int c = tid & 127, j4 = 4 * c, half = tid >> 7;
                ULL acc[M][2];
                if (half == 0) {
                    const ULL bl = *(const ULL*)(b1h + j4);
                    const ULL bh = *(const ULL*)(b1h + j4 + 2);
                    #pragma unroll
                    for (int m = 0; m < M; ++m) { acc[m][0] = bl; acc[m][1] = bh; }
                } else {
                    #pragma unroll
                    for (int m = 0; m < M; ++m) { acc[m][0] = 0ULL; acc[m][1] = 0ULL; }
                }
                dotp4<160, WH, KHX>(acc, W1h + (size_t)(half * 160) * WH + j4,
                                    hx + half * 160);
                if (half == 1) {
                    #pragma unroll
                    for (int m = 0; m < M; ++m) {
                        rdA[(m * 128 + c) * 2]     = acc[m][0];
                        rdA[(m * 128 + c) * 2 + 1] = acc[m][1];
                    }
                }
                __syncthreads();
                if (half == 0) {
                    #pragma unroll
                    for (int m = 0; m < M; ++m) {
                        const ULL v0 = fadd2(acc[m][0], rdA[(m * 128 + c) * 2]);
                        const ULL v1 = fadd2(acc[m][1], rdA[(m * 128 + c) * 2 + 1]);
                        float z0, z1, z2, z3;
                        unpack2(v0, z0, z1); unpack2(v1, z2, z3);
                        const float s0 = silu_f(z0), s1 = silu_f(z1);
                        const float s2 = silu_f(z2), s3 = silu_f(z3);
                        ULL* ap = a2 + m * WH + j4;
                        ap[0] = pack2(s0, s0); ap[1] = pack2(s1, s1);
                        ap[2] = pack2(s2, s2); ap[3] = pack2(s3, s3);
                    }
                }
            }
            __syncthreads();

            // phase 2: h' = a @ W2h + b2h. 4 cols/thread, split-K 4-way.
            {
                const int c = tid & 63, j4 = 4 * c, q = tid >> 6;
                ULL acc[M][2];
                if (q == 0) {
                    const ULL bl = *(const ULL*)(b2h + j4);
                    const ULL bh = *(const ULL*)(b2h + j4 + 2);
                    #pragma unroll
                    for (int m = 0; m < M; ++m) { acc[m][0] = bl; acc[m][1] = bh; }
                } else {
                    #pragma unroll
                    for (int m = 0; m < M; ++m) { acc[m][0] = 0ULL; acc[m][1] = 0ULL; }
                }
                dotp4<128, H, WH>(acc, W2h + (size_t)(q * 128) * H + j4,
                                  a2 + q * 128);
                if (q > 0) {
                    ULL* rp = rdB + (((q - 1) * M) * 64) * 2;
                    #pragma unroll
                    for (int m = 0; m < M; ++m) {
                        rp[(m * 64 + c) * 2]     = acc[m][0];
                        rp[(m * 64 + c) * 2 + 1] = acc[m][1];
                    }
                }
                __syncthreads();
                if (q == 0) {
                    #pragma unroll
                    for (int m = 0; m < M; ++m) {
                        ULL v0 = acc[m][0], v1 = acc[m][1];
                        #pragma unroll
                        for (int qi = 0; qi < 3; ++qi) {
                            const ULL* rp = rdB + ((qi * M + m) * 64 + c) * 2;
                            v0 = fadd2(v0, rp[0]);
                            v1 = fadd2(v1, rp[1]);
                        }
                        float h0, h1, h2, h3;
                        unpack2(v0, h0, h1); unpack2(v1, h2, h3);
                        *(float4*)(hid + ((size_t)(t + 1) * B + (b0 + m)) * H + j4)
                            = make_float4(h0, h1, h2, h3);
                        ULL* hp = hx + m * KHX + j4;
                        hp[0] = pack2(h0, h0); hp[1] = pack2(h1, h1);
                        hp[2] = pack2(h2, h2); hp[3] = pack2(h3, h3);
                    }
                    __threadfence();   // publish hid before progress release
                }
            }
            __syncthreads();
            if (tid == 0) rel_store(&g_progress[bid], (unsigned)(t + 1));
        }
    } else {
        // ========================= y branch (ymlp) ==========================
        const int i  = bid - REC_CTAS;
        const int t  = i >> 3;                // time step
        const int bt = i & 7;                 // batch tile
        const int b0 = bt * YROWS;

        // wait for the 8 recurrent CTAs covering rows [b0, b0+32)
        if (tid == 0) {
            const int c0 = b0 / M;
            const unsigned need = (unsigned)(t + 1);
            #pragma unroll
            for (int c = 0; c < YROWS / M; ++c) {
                while (acq_load(&g_progress[c0 + c]) < need) __nanosleep(256);
            }
        }
        __syncthreads();

        // load h rows (dup-packed) into smem
        ULL* hs = sm;             // [YROWS][H]
        ULL* us = sm + US_OFF;    // [YROWS][H]
        const float* hrow = hid + ((size_t)(t + 1) * B + b0) * H;
        for (int e = tid; e < YROWS * (H / 4); e += T) {
            const int r = e >> 6, c4 = (e & 63) * 4;
            const float4 v = *(const float4*)(hrow + (size_t)r * H + c4);
            ULL* dp = hs + r * H + c4;
            dp[0] = pack2(v.x, v.x); dp[1] = pack2(v.y, v.y);
            dp[2] = pack2(v.z, v.z); dp[3] = pack2(v.w, v.w);
        }
        __syncthreads();

        // GEMM1: u = silu(h @ W1y + b1y)   [32 x 256]
        {
            const int c = tid & 127, j2 = 2 * c, half = tid >> 7, r0 = half * 16;
            ULL acc[16];
            const ULL bias = *(const ULL*)(b1y + j2);
            #pragma unroll
            for (int r = 0; r < 16; ++r) acc[r] = bias;
            ydot<16, WY>(acc, W1y + j2, hs + r0 * H);
            #pragma unroll
            for (int r = 0; r < 16; ++r) {
                float z0, z1; unpack2(acc[r], z0, z1);
                const float s0 = silu_f(z0), s1 = silu_f(z1);
                ULL* up = us + (r0 + r) * H + j2;
                up[0] = pack2(s0, s0); up[1] = pack2(s1, s1);
            }
        }
        __syncthreads();

        // GEMM2: y = u @ W2y + b2y   [32 x 64] -> outs
        {
            const int cp = tid & 31, j2 = 2 * cp, g = tid >> 5, r0 = g * 4;
            ULL acc[4];
            const ULL bias = *(const ULL*)(b2y + j2);
            #pragma unroll
            for (int r = 0; r < 4; ++r) acc[r] = bias;
            ydot<4, DOUT>(acc, W2y + j2, us + r0 * H);
            #pragma unroll
            for (int r = 0; r < 4; ++r) {
                float y0, y1; unpack2(acc[r], y0, y1);
                *(float2*)(outs + ((size_t)(b0 + r0 + r) * S + t) * DOUT + j2)
                    = make_float2(y0, y1);
            }
        }
    }
}

extern "C" void kernel_launch(void* const* d_in, const int* in_sizes, int n_in,
                              void* d_out, int out_size) {
    (void)in_sizes; (void)n_in; (void)out_size;
    const float* x   = (const float*)d_in[0];
    const float* W1h = (const float*)d_in[1];
    const float* b1h = (const float*)d_in[2];
    const float* W2h = (const float*)d_in[3];
    const float* b2h = (const float*)d_in[4];
    const float* W1y = (const float*)d_in[5];
    const float* b1y = (const float*)d_in[6];
    const float* W2y = (const float*)d_in[7];
    const float* b2y = (const float*)d_in[8];

    float* outs = (float*)d_out;                       // [B, S, DOUT]
    float* hid  = outs + (size_t)B * S * DOUT;         // [S+1, B, H]

    cudaFuncSetAttribute(rnn_fused_kernel,
                         cudaFuncAttributeMaxDynamicSharedMemorySize,
                         DSMEM_BYTES);

    init_progress_kernel<<<1, 64>>>();
    rnn_fused_kernel<<<GRID, T, DSMEM_BYTES>>>(x, W1h, b1h, W2h, b2h,
                                               W1y, b1y, W2y, b2y, outs, hid);
}

// round 16
// speedup vs baseline: 1.8828x; 1.0346x over previous
#include <cuda_runtime.h>
#include <cstdint>

// ============================================================================
// GeneralRNN: h_t = hmlp([h_{t-1}, x_t]); y_t = ymlp(h_t)
// B=256, S=1024, D_IN=64, H=256, W_H=512, W_Y=256, D_OUT=64 (fp32).
//
// R15 design (changes vs R14 marked *):
//  * Recurrent part (hmlp only): 64 persistent CTAs x 4 batch rows.
//    *T=512 threads (16 warps/SM, was 8): R14 showed the recurrent SMs stuck
//    at ~2.5x their FFMA/L1tex floor with only 2 warps/SMSP to hide L2
//    latency. Phase 1 now splits K=320 4-way, phase 2 splits K=512 8-way.
//  * ymlp (no recurrence): 8192 extra CTAs of the same launch on the ~84
//    idle SMs, consuming hid via release/acquire progress counters.
//    *Re-tiled for 512 threads; U=8 load buffers for the 128-reg/thread cap.
// ============================================================================

#define ULL unsigned long long

static constexpr int B    = 256;
static constexpr int S    = 1024;
static constexpr int DIN  = 64;
static constexpr int H    = 256;
static constexpr int WH   = 512;
static constexpr int WY   = 256;
static constexpr int DOUT = 64;
static constexpr int KHX  = H + DIN;       // 320

static constexpr int M        = 4;         // batch rows per recurrent CTA
static constexpr int REC_CTAS = B / M;     // 64
static constexpr int T        = 512;
static constexpr int YROWS    = 32;        // rows per y-tile CTA
static constexpr int YTILES   = S * (B / YROWS);   // 8192
static constexpr int GRID     = REC_CTAS + YTILES;

// dyn smem layout in ULL units ------------------------------------------------
static constexpr int HX_OFF   = 0;                       // [M][KHX]        1280
static constexpr int A2_OFF   = HX_OFF + M * KHX;        // [M][WH]         2048
static constexpr int REDA_OFF = A2_OFF + M * WH;         // [3][M][128][2]  3072
static constexpr int REDB_OFF = REDA_OFF + 3 * M * 128 * 2; // [7][M][64][2] 3584
// y-branch union: hs [32][256] at 0, us [32][256] at 8192
static constexpr int US_OFF   = YROWS * H;               // 8192
static constexpr int DSMEM_ULL = 2 * YROWS * H;          // 16384 ULL = 128 KB
static constexpr int DSMEM_BYTES = DSMEM_ULL * 8;

__device__ unsigned g_progress[REC_CTAS];

// ---- packed f32x2 helpers (sm_100+) ----------------------------------------
__device__ __forceinline__ void ffma2(ULL& c, ULL a, ULL b) {
    asm("fma.rn.f32x2 %0, %1, %2, %0;" : "+l"(c) : "l"(a), "l"(b));
}
__device__ __forceinline__ ULL fadd2(ULL a, ULL b) {
    ULL r; asm("add.rn.f32x2 %0, %1, %2;" : "=l"(r) : "l"(a), "l"(b)); return r;
}
__device__ __forceinline__ ULL pack2(float lo, float hi) {
    ULL r;
    asm("mov.b64 %0, {%1, %2};"
        : "=l"(r) : "r"(__float_as_uint(lo)), "r"(__float_as_uint(hi)));
    return r;
}
__device__ __forceinline__ void unpack2(ULL v, float& lo, float& hi) {
    unsigned int a, b;
    asm("mov.b64 {%0, %1}, %2;" : "=r"(a), "=r"(b) : "l"(v));
    lo = __uint_as_float(a); hi = __uint_as_float(b);
}
__device__ __forceinline__ float silu_f(float z) {
    return z / (1.0f + __expf(-z));
}
__device__ __forceinline__ ULL ldgw(const float* p) {       // 64-bit weight load
    return __ldg(reinterpret_cast<const ULL*>(p));
}
__device__ __forceinline__ ulonglong2 ldgw4(const float* p) { // 128-bit weight load
    return __ldg(reinterpret_cast<const ulonglong2*>(p));
}
__device__ __forceinline__ void rel_store(unsigned* p, unsigned v) {
    asm volatile("st.release.gpu.b32 [%0], %1;" :: "l"(p), "r"(v) : "memory");
}
__device__ __forceinline__ unsigned acq_load(const unsigned* p) {
    unsigned v;
    asm volatile("ld.acquire.gpu.b32 %0, [%1];" : "=r"(v) : "l"(p) : "memory");
    return v;
}

// ----------------------------------------------------------------------------
// Recurrent dot: 4 output cols per thread, M batch rows, double-buffered
// LDG.128 weight stream. acc[m][0] = cols (j4,j4+1), acc[m][1] = (j4+2,j4+3).
// KLEN must be a multiple of 16. act: dup-packed, element stride AS per row m.
// ----------------------------------------------------------------------------
template<int KLEN, int WS, int AS>
__device__ __forceinline__ void dotp4(ULL acc[M][2],
                                      const float* __restrict__ wp,
                                      const ULL* __restrict__ act)
{
    constexpr int U = 8;
    static_assert(KLEN % (2 * U) == 0, "KLEN % 16");
    ulonglong2 wa[U], wb[U];

    #pragma unroll
    for (int u = 0; u < U; ++u) wa[u] = ldgw4(wp + (size_t)u * WS);

    #pragma unroll 1
    for (int k0 = 0; k0 < KLEN; k0 += 2 * U) {
        #pragma unroll
        for (int u = 0; u < U; ++u)
            wb[u] = ldgw4(wp + (size_t)(k0 + U + u) * WS);

        #pragma unroll
        for (int u = 0; u < U; u += 2) {
            #pragma unroll
            for (int m = 0; m < M; ++m) {
                const ulonglong2 hv =
                    *reinterpret_cast<const ulonglong2*>(act + m * AS + k0 + u);
                ffma2(acc[m][0], hv.x, wa[u].x);
                ffma2(acc[m][1], hv.x, wa[u].y);
                ffma2(acc[m][0], hv.y, wa[u + 1].x);
                ffma2(acc[m][1], hv.y, wa[u + 1].y);
            }
        }
        #pragma unroll
        for (int u = 0; u < U; ++u) {
            const int kk = k0 + 2 * U + u;
            if (kk < KLEN) wa[u] = ldgw4(wp + (size_t)kk * WS);
        }
        #pragma unroll
        for (int u = 0; u < U; u += 2) {
            #pragma unroll
            for (int m = 0; m < M; ++m) {
                const ulonglong2 hv =
                    *reinterpret_cast<const ulonglong2*>(act + m * AS + k0 + U + u);
                ffma2(acc[m][0], hv.x, wb[u].x);
                ffma2(acc[m][1], hv.x, wb[u].y);
                ffma2(acc[m][0], hv.y, wb[u + 1].x);
                ffma2(acc[m][1], hv.y, wb[u + 1].y);
            }
        }
    }
}

// ----------------------------------------------------------------------------
// y-branch dot: R rows x 2 cols per thread over K=256, LDG.64 weight stream.
// ----------------------------------------------------------------------------
template<int R, int WS>
__device__ __forceinline__ void ydot(ULL acc[R],
                                     const float* __restrict__ wp,
                                     const ULL* __restrict__ act)  // row stride H
{
    constexpr int U = 8;
    ULL wa[U], wb[U];
    #pragma unroll
    for (int u = 0; u < U; ++u) wa[u] = ldgw(wp + (size_t)u * WS);

    #pragma unroll 1
    for (int k0 = 0; k0 < 256; k0 += 2 * U) {
        #pragma unroll
        for (int u = 0; u < U; ++u)
            wb[u] = ldgw(wp + (size_t)(k0 + U + u) * WS);
        #pragma unroll
        for (int u = 0; u < U; u += 2) {
            #pragma unroll
            for (int r = 0; r < R; ++r) {
                const ulonglong2 hv =
                    *reinterpret_cast<const ulonglong2*>(act + r * H + k0 + u);
                ffma2(acc[r], hv.x, wa[u]);
                ffma2(acc[r], hv.y, wa[u + 1]);
            }
        }
        #pragma unroll
        for (int u = 0; u < U; ++u) {
            const int kk = k0 + 2 * U + u;
            if (kk < 256) wa[u] = ldgw(wp + (size_t)kk * WS);
        }
        #pragma unroll
        for (int u = 0; u < U; u += 2) {
            #pragma unroll
            for (int r = 0; r < R; ++r) {
                const ulonglong2 hv =
                    *reinterpret_cast<const ulonglong2*>(act + r * H + k0 + U + u);
                ffma2(acc[r], hv.x, wb[u]);
                ffma2(acc[r], hv.y, wb[u + 1]);
            }
        }
    }
}

__global__ void init_progress_kernel() {
    if (threadIdx.x < REC_CTAS) g_progress[threadIdx.x] = 0u;
}

__global__ __launch_bounds__(T, 1)
void rnn_fused_kernel(
    const float* __restrict__ x,    // [B, S, DIN]
    const float* __restrict__ W1h,  // [KHX, WH]
    const float* __restrict__ b1h,
    const float* __restrict__ W2h,  // [WH, H]
    const float* __restrict__ b2h,
    const float* __restrict__ W1y,  // [H, WY]
    const float* __restrict__ b1y,
    const float* __restrict__ W2y,  // [WY, DOUT]
    const float* __restrict__ b2y,
    float* __restrict__ outs,       // [B, S, DOUT]
    float* __restrict__ hid)        // [S+1, B, H]
{
    extern __shared__ __align__(16) ULL sm[];
    const int tid = threadIdx.x;
    const int bid = blockIdx.x;

    if (bid < REC_CTAS) {
        // ====================== recurrent branch (hmlp) =====================
        ULL* hx  = sm + HX_OFF;     // [M][KHX] dup-packed
        ULL* a2  = sm + A2_OFF;     // [M][WH]  dup-packed
        ULL* rdA = sm + REDA_OFF;   // [3][M][128][2]
        ULL* rdB = sm + REDB_OFF;   // [7][M][64][2]
        const int b0 = bid * M;

        for (int i = tid; i < M * H; i += T) {
            const int m = i / H, j = i % H;
            hx[m * KHX + j] = 0ULL;
            hid[(size_t)(b0 + m) * H + j] = 0.0f;   // hiddens[0] = 0
        }
        __syncthreads();

        for (int t = 0; t < S; ++t) {
            // x_t into hx cols [H, H+DIN)
            if (tid < M * DIN) {
                const int m = tid >> 6, d = tid & 63;
                const float xv = x[((size_t)(b0 + m) * S + t) * DIN + d];
                hx[m * KHX + H + d] = pack2(xv, xv);
            }
            __syncthreads();

            // phase 1: a = silu(hx @ W1h + b1h). 4 cols/thread, split-K 4-way.
            {
                const int c = tid & 127, j4 = 4 * c, part = tid >> 7;  // 0..3
                ULL acc[M][2];
                if (part == 0) {
                    const ULL bl = *(const ULL*)(b1h + j4);
                    const ULL bh = *(const ULL*)(b1h + j4 + 2);
                    #pragma unroll
                    for (int m = 0; m < M; ++m) { acc[m][0] = bl; acc[m][1] = bh; }
                } else {
                    #pragma unroll
                    for (int m = 0; m < M; ++m) { acc[m][0] = 0ULL; acc[m][1] = 0ULL; }
                }
                dotp4<80, WH, KHX>(acc, W1h + (size_t)(part * 80) * WH + j4,
                                   hx + part * 80);
                if (part > 0) {
                    #pragma unroll
                    for (int m = 0; m < M; ++m) {
                        ULL* rp = rdA + (((part - 1) * M + m) * 128 + c) * 2;
                        rp[0] = acc[m][0];
                        rp[1] = acc[m][1];
                    }
                }
                __syncthreads();
                if (part == 0) {
                    #pragma unroll
                    for (int m = 0; m < M; ++m) {
                        ULL v0 = acc[m][0], v1 = acc[m][1];
                        #pragma unroll
                        for (int p = 0; p < 3; ++p) {
                            const ULL* rp = rdA + ((p * M + m) * 128 + c) * 2;
                            v0 = fadd2(v0, rp[0]);
                            v1 = fadd2(v1, rp[1]);
                        }
                        float z0, z1, z2, z3;
                        unpack2(v0, z0, z1); unpack2(v1, z2, z3);
                        const float s0 = silu_f(z0), s1 = silu_f(z1);
                        const float s2 = silu_f(z2), s3 = silu_f(z3);
                        ULL* ap = a2 + m * WH + j4;
                        ap[0] = pack2(s0, s0); ap[1] = pack2(s1, s1);
                        ap[2] = pack2(s2, s2); ap[3] = pack2(s3, s3);
                    }
                }
            }
            __syncthreads();

            // phase 2: h' = a @ W2h + b2h. 4 cols/thread, split-K 8-way.
            {
                const int c = tid & 63, j4 = 4 * c, q = tid >> 6;  // 0..7
                ULL acc[M][2];
                if (q == 0) {
                    const ULL bl = *(const ULL*)(b2h + j4);
                    const ULL bh = *(const ULL*)(b2h + j4 + 2);
                    #pragma unroll
                    for (int m = 0; m < M; ++m) { acc[m][0] = bl; acc[m][1] = bh; }
                } else {
                    #pragma unroll
                    for (int m = 0; m < M; ++m) { acc[m][0] = 0ULL; acc[m][1] = 0ULL; }
                }
                dotp4<64, H, WH>(acc, W2h + (size_t)(q * 64) * H + j4,
                                 a2 + q * 64);
                if (q > 0) {
                    #pragma unroll
                    for (int m = 0; m < M; ++m) {
                        ULL* rp = rdB + (((q - 1) * M + m) * 64 + c) * 2;
                        rp[0] = acc[m][0];
                        rp[1] = acc[m][1];
                    }
                }
                __syncthreads();
                if (q == 0) {
                    #pragma unroll
                    for (int m = 0; m < M; ++m) {
                        ULL v0 = acc[m][0], v1 = acc[m][1];
                        #pragma unroll
                        for (int qi = 0; qi < 7; ++qi) {
                            const ULL* rp = rdB + ((qi * M + m) * 64 + c) * 2;
                            v0 = fadd2(v0, rp[0]);
                            v1 = fadd2(v1, rp[1]);
                        }
                        float h0, h1, h2, h3;
                        unpack2(v0, h0, h1); unpack2(v1, h2, h3);
                        *(float4*)(hid + ((size_t)(t + 1) * B + (b0 + m)) * H + j4)
                            = make_float4(h0, h1, h2, h3);
                        ULL* hp = hx + m * KHX + j4;
                        hp[0] = pack2(h0, h0); hp[1] = pack2(h1, h1);
                        hp[2] = pack2(h2, h2); hp[3] = pack2(h3, h3);
                    }
                    __threadfence();   // publish hid before progress release
                }
            }
            __syncthreads();
            if (tid == 0) rel_store(&g_progress[bid], (unsigned)(t + 1));
        }
    } else {
        // ========================= y branch (ymlp) ==========================
        const int i  = bid - REC_CTAS;
        const int t  = i >> 3;                // time step
        const int bt = i & 7;                 // batch tile
        const int b0 = bt * YROWS;

        // wait for the 8 recurrent CTAs covering rows [b0, b0+32)
        if (tid == 0) {
            const int c0 = b0 / M;
            const unsigned need = (unsigned)(t + 1);
            #pragma unroll
            for (int c = 0; c < YROWS / M; ++c) {
                while (acq_load(&g_progress[c0 + c]) < need) __nanosleep(256);
            }
        }
        __syncthreads();

        // load h rows (dup-packed) into smem
        ULL* hs = sm;             // [YROWS][H]
        ULL* us = sm + US_OFF;    // [YROWS][H]
        const float* hrow = hid + ((size_t)(t + 1) * B + b0) * H;
        for (int e = tid; e < YROWS * (H / 4); e += T) {
            const int r = e >> 6, c4 = (e & 63) * 4;
            const float4 v = *(const float4*)(hrow + (size_t)r * H + c4);
            ULL* dp = hs + r * H + c4;
            dp[0] = pack2(v.x, v.x); dp[1] = pack2(v.y, v.y);
            dp[2] = pack2(v.z, v.z); dp[3] = pack2(v.w, v.w);
        }
        __syncthreads();

        // GEMM1: u = silu(h @ W1y + b1y)   [32 x 256]
        {
            const int c = tid & 127, j2 = 2 * c, grp = tid >> 7, r0 = grp * 8;
            ULL acc[8];
            const ULL bias = *(const ULL*)(b1y + j2);
            #pragma unroll
            for (int r = 0; r < 8; ++r) acc[r] = bias;
            ydot<8, WY>(acc, W1y + j2, hs + r0 * H);
            #pragma unroll
            for (int r = 0; r < 8; ++r) {
                float z0, z1; unpack2(acc[r], z0, z1);
                const float s0 = silu_f(z0), s1 = silu_f(z1);
                ULL* up = us + (r0 + r) * H + j2;
                up[0] = pack2(s0, s0); up[1] = pack2(s1, s1);
            }
        }
        __syncthreads();

        // GEMM2: y = u @ W2y + b2y   [32 x 64] -> outs
        {
            const int cp = tid & 31, j2 = 2 * cp, g = tid >> 5, r0 = g * 2;
            ULL acc[2];
            const ULL bias = *(const ULL*)(b2y + j2);
            #pragma unroll
            for (int r = 0; r < 2; ++r) acc[r] = bias;
            ydot<2, DOUT>(acc, W2y + j2, us + r0 * H);
            #pragma unroll
            for (int r = 0; r < 2; ++r) {
                float y0, y1; unpack2(acc[r], y0, y1);
                *(float2*)(outs + ((size_t)(b0 + r0 + r) * S + t) * DOUT + j2)
                    = make_float2(y0, y1);
            }
        }
    }
}

extern "C" void kernel_launch(void* const* d_in, const int* in_sizes, int n_in,
                              void* d_out, int out_size) {
    (void)in_sizes; (void)n_in; (void)out_size;
    const float* x   = (const float*)d_in[0];
    const float* W1h = (const float*)d_in[1];
    const float* b1h = (const float*)d_in[2];
    const float* W2h = (const float*)d_in[3];
    const float* b2h = (const float*)d_in[4];
    const float* W1y = (const float*)d_in[5];
    const float* b1y = (const float*)d_in[6];
    const float* W2y = (const float*)d_in[7];
    const float* b2y = (const float*)d_in[8];

    float* outs = (float*)d_out;                       // [B, S, DOUT]
    float* hid  = outs + (size_t)B * S * DOUT;         // [S+1, B, H]

    cudaFuncSetAttribute(rnn_fused_kernel,
                         cudaFuncAttributeMaxDynamicSharedMemorySize,
                         DSMEM_BYTES);

    init_progress_kernel<<<1, 64>>>();
    rnn_fused_kernel<<<GRID, T, DSMEM_BYTES>>>(x, W1h, b1h, W2h, b2h,
                                               W1y, b1y, W2y, b2y, outs, hid);
}

// round 17
// speedup vs baseline: 2.3550x; 1.2508x over previous
#include <cuda_runtime.h>
#include <cstdint>

// ============================================================================
// GeneralRNN: h_t = hmlp([h_{t-1}, x_t]); y_t = ymlp(h_t)
// B=256, S=1024, D_IN=64, H=256, W_H=512, W_Y=256, D_OUT=64 (fp32).
//
// R16 design (changes vs R15 marked *):
//  * Recurrent hmlp: 64 persistent CTAs x 4 batch rows, T=512.
//    *Mixed-pair FFMA2: activations stored PLAIN fp32 batch-major act[k][m];
//    one uniform LDS.128 per k serves all 4 rows (R15 needed two dup-packed
//    LDS.128 per k). Pairing: acc=(y[m0][j],y[m1][j+1]) uses natural packed
//    operands; the sibling pair uses a 2-MOV swapped weight pair. R15 ncu
//    showed recurrent SMs at ~100% L1tex — this halves the LDS stream.
//    *x_{t+1} merged into phase-2 epilogue (one fewer sync per step).
//    *fence+progress-release by tid0 only, after the final sync.
//  * ymlp (no recurrence): unchanged from R15 — 8192 trailing CTAs on the
//    idle SMs, gated by per-recurrent-CTA release/acquire progress counters.
// ============================================================================

#define ULL unsigned long long

static constexpr int B    = 256;
static constexpr int S    = 1024;
static constexpr int DIN  = 64;
static constexpr int H    = 256;
static constexpr int WH   = 512;
static constexpr int WY   = 256;
static constexpr int DOUT = 64;
static constexpr int KHX  = H + DIN;       // 320

static constexpr int M        = 4;         // batch rows per recurrent CTA
static constexpr int REC_CTAS = B / M;     // 64
static constexpr int T        = 512;
static constexpr int YROWS    = 32;        // rows per y-tile CTA
static constexpr int YTILES   = S * (B / YROWS);   // 8192
static constexpr int GRID     = REC_CTAS + YTILES;

// recurrent smem layout (ULL units). Activations are plain float, batch-major
// with row stride 8 floats (32B) so LDS.128 at k*32 is always aligned.
static constexpr int HX_OFF   = 0;                        // float[KHX][8] =1280 ULL
static constexpr int A2_OFF   = HX_OFF + KHX * 8 / 2;     // float[WH][8] = 2048 ULL
static constexpr int RDA_OFF  = A2_OFF + WH * 8 / 2;      // ULL[3][128][10]
static constexpr int RDB_OFF  = RDA_OFF + 3 * 128 * 10;   // ULL[7][64][10]
// y-branch union: hs [32][256] dup-packed at 0, us at 8192
static constexpr int US_OFF   = YROWS * H;                // 8192
static constexpr int DSMEM_ULL = 2 * YROWS * H;           // 16384 ULL = 128 KB
static constexpr int DSMEM_BYTES = DSMEM_ULL * 8;

__device__ unsigned g_progress[REC_CTAS];

// ---- packed f32x2 helpers (sm_100+) ----------------------------------------
__device__ __forceinline__ void ffma2(ULL& c, ULL a, ULL b) {
    asm("fma.rn.f32x2 %0, %1, %2, %0;" : "+l"(c) : "l"(a), "l"(b));
}
__device__ __forceinline__ ULL fadd2(ULL a, ULL b) {
    ULL r; asm("add.rn.f32x2 %0, %1, %2;" : "=l"(r) : "l"(a), "l"(b)); return r;
}
__device__ __forceinline__ ULL pack2(float lo, float hi) {
    ULL r;
    asm("mov.b64 %0, {%1, %2};"
        : "=l"(r) : "r"(__float_as_uint(lo)), "r"(__float_as_uint(hi)));
    return r;
}
__device__ __forceinline__ void unpack2(ULL v, float& lo, float& hi) {
    unsigned int a, b;
    asm("mov.b64 {%0, %1}, %2;" : "=r"(a), "=r"(b) : "l"(v));
    lo = __uint_as_float(a); hi = __uint_as_float(b);
}
__device__ __forceinline__ ULL swp(ULL v) {   // swap halves of a packed pair
    unsigned int a, b;
    asm("mov.b64 {%0, %1}, %2;" : "=r"(a), "=r"(b) : "l"(v));
    ULL r;
    asm("mov.b64 %0, {%1, %2};" : "=l"(r) : "r"(b), "r"(a));
    return r;
}
__device__ __forceinline__ float silu_f(float z) {
    return z / (1.0f + __expf(-z));
}
__device__ __forceinline__ ULL ldgw(const float* p) {
    return __ldg(reinterpret_cast<const ULL*>(p));
}
__device__ __forceinline__ ulonglong2 ldgw4(const float* p) {
    return __ldg(reinterpret_cast<const ulonglong2*>(p));
}
__device__ __forceinline__ void rel_store(unsigned* p, unsigned v) {
    asm volatile("st.release.gpu.b32 [%0], %1;" :: "l"(p), "r"(v) : "memory");
}
__device__ __forceinline__ unsigned acq_load(const unsigned* p) {
    unsigned v;
    asm volatile("ld.acquire.gpu.b32 %0, [%1];" : "=r"(v) : "l"(p) : "memory");
    return v;
}

// ----------------------------------------------------------------------------
// Mixed-pair dot: 4 output cols (j0..j3) x 4 batch rows per thread.
// acc pairing (per thread):
//   acc[0]=(y[m0][j0],y[m1][j1])  acc[1]=(y[m0][j1],y[m1][j0])
//   acc[2]=(y[m0][j2],y[m1][j3])  acc[3]=(y[m0][j3],y[m1][j2])
//   acc[4..7] = same with rows m2,m3
// act: plain fp32, batch-major, row stride 8 floats: act[k*8 + m].
// Weights double-buffered via LDG.128 (U=8 blocks of 16 k).
// ----------------------------------------------------------------------------
template<int KLEN, int WS>
__device__ __forceinline__ void dotp_mixed(ULL acc[8],
                                           const float* __restrict__ wp,
                                           const float* __restrict__ act)
{
    constexpr int U = 8;
    static_assert(KLEN % (2 * U) == 0, "KLEN % 16");
    ulonglong2 wa[U], wb[U];

    #pragma unroll
    for (int u = 0; u < U; ++u) wa[u] = ldgw4(wp + (size_t)u * WS);

    #pragma unroll 1
    for (int k0 = 0; k0 < KLEN; k0 += 2 * U) {
        #pragma unroll
        for (int u = 0; u < U; ++u)
            wb[u] = ldgw4(wp + (size_t)(k0 + U + u) * WS);

        #pragma unroll
        for (int u = 0; u < U; ++u) {
            const ulonglong2 hv =
                *reinterpret_cast<const ulonglong2*>(act + (size_t)(k0 + u) * 8);
            const ULL w01 = wa[u].x, w23 = wa[u].y;
            const ULL w10 = swp(w01), w32 = swp(w23);
            ffma2(acc[0], hv.x, w01); ffma2(acc[1], hv.x, w10);
            ffma2(acc[2], hv.x, w23); ffma2(acc[3], hv.x, w32);
            ffma2(acc[4], hv.y, w01); ffma2(acc[5], hv.y, w10);
            ffma2(acc[6], hv.y, w23); ffma2(acc[7], hv.y, w32);
        }
        #pragma unroll
        for (int u = 0; u < U; ++u) {
            const int kk = k0 + 2 * U + u;
            if (kk < KLEN) wa[u] = ldgw4(wp + (size_t)kk * WS);
        }
        #pragma unroll
        for (int u = 0; u < U; ++u) {
            const ulonglong2 hv =
                *reinterpret_cast<const ulonglong2*>(act + (size_t)(k0 + U + u) * 8);
            const ULL w01 = wb[u].x, w23 = wb[u].y;
            const ULL w10 = swp(w01), w32 = swp(w23);
            ffma2(acc[0], hv.x, w01); ffma2(acc[1], hv.x, w10);
            ffma2(acc[2], hv.x, w23); ffma2(acc[3], hv.x, w32);
            ffma2(acc[4], hv.y, w01); ffma2(acc[5], hv.y, w10);
            ffma2(acc[6], hv.y, w23); ffma2(acc[7], hv.y, w32);
        }
    }
}

// Unscramble the 8 mixed pairs into y[m][0..3].
__device__ __forceinline__ void unscramble(const ULL v[8], float y[M][4]) {
    float l0,h0,l1,h1,l2,h2,l3,h3;
    unpack2(v[0],l0,h0); unpack2(v[1],l1,h1); unpack2(v[2],l2,h2); unpack2(v[3],l3,h3);
    y[0][0]=l0; y[0][1]=l1; y[0][2]=l2; y[0][3]=l3;
    y[1][0]=h1; y[1][1]=h0; y[1][2]=h3; y[1][3]=h2;
    unpack2(v[4],l0,h0); unpack2(v[5],l1,h1); unpack2(v[6],l2,h2); unpack2(v[7],l3,h3);
    y[2][0]=l0; y[2][1]=l1; y[2][2]=l2; y[2][3]=l3;
    y[3][0]=h1; y[3][1]=h0; y[3][2]=h3; y[3][3]=h2;
}

// ----------------------------------------------------------------------------
// y-branch dot (unchanged from R15): R rows x 2 cols per thread over K=256.
// ----------------------------------------------------------------------------
template<int R, int WS>
__device__ __forceinline__ void ydot(ULL acc[R],
                                     const float* __restrict__ wp,
                                     const ULL* __restrict__ act)  // row stride H
{
    constexpr int U = 8;
    ULL wa[U], wb[U];
    #pragma unroll
    for (int u = 0; u < U; ++u) wa[u] = ldgw(wp + (size_t)u * WS);

    #pragma unroll 1
    for (int k0 = 0; k0 < 256; k0 += 2 * U) {
        #pragma unroll
        for (int u = 0; u < U; ++u)
            wb[u] = ldgw(wp + (size_t)(k0 + U + u) * WS);
        #pragma unroll
        for (int u = 0; u < U; u += 2) {
            #pragma unroll
            for (int r = 0; r < R; ++r) {
                const ulonglong2 hv =
                    *reinterpret_cast<const ulonglong2*>(act + r * H + k0 + u);
                ffma2(acc[r], hv.x, wa[u]);
                ffma2(acc[r], hv.y, wa[u + 1]);
            }
        }
        #pragma unroll
        for (int u = 0; u < U; ++u) {
            const int kk = k0 + 2 * U + u;
            if (kk < 256) wa[u] = ldgw(wp + (size_t)kk * WS);
        }
        #pragma unroll
        for (int u = 0; u < U; u += 2) {
            #pragma unroll
            for (int r = 0; r < R; ++r) {
                const ulonglong2 hv =
                    *reinterpret_cast<const ulonglong2*>(act + r * H + k0 + U + u);
                ffma2(acc[r], hv.x, wb[u]);
                ffma2(acc[r], hv.y, wb[u + 1]);
            }
        }
    }
}

__global__ void init_progress_kernel() {
    if (threadIdx.x < REC_CTAS) g_progress[threadIdx.x] = 0u;
}

__global__ __launch_bounds__(T, 1)
void rnn_fused_kernel(
    const float* __restrict__ x,    // [B, S, DIN]
    const float* __restrict__ W1h,  // [KHX, WH]
    const float* __restrict__ b1h,
    const float* __restrict__ W2h,  // [WH, H]
    const float* __restrict__ b2h,
    const float* __restrict__ W1y,  // [H, WY]
    const float* __restrict__ b1y,
    const float* __restrict__ W2y,  // [WY, DOUT]
    const float* __restrict__ b2y,
    float* __restrict__ outs,       // [B, S, DOUT]
    float* __restrict__ hid)        // [S+1, B, H]
{
    extern __shared__ __align__(16) ULL sm[];
    const int tid = threadIdx.x;
    const int bid = blockIdx.x;

    if (bid < REC_CTAS) {
        // ====================== recurrent branch (hmlp) =====================
        float* hxf = reinterpret_cast<float*>(sm + HX_OFF);  // [KHX][8]
        float* a2f = reinterpret_cast<float*>(sm + A2_OFF);  // [WH][8]
        ULL*   rdA = sm + RDA_OFF;                           // [3][128][10]
        ULL*   rdB = sm + RDB_OFF;                           // [7][64][10]
        const int b0 = bid * M;

        // h0 = 0; hiddens[0] = 0; x_0 into hx
        for (int i = tid; i < KHX * 8; i += T) hxf[i] = 0.0f;
        for (int i = tid; i < M * H; i += T)
            hid[(size_t)(b0 + i / H) * H + (i % H)] = 0.0f;
        __syncthreads();
        if (tid < M * DIN) {
            const int m = tid & 3, d = tid >> 2;
            hxf[(H + d) * 8 + m] = x[((size_t)(b0 + m) * S + 0) * DIN + d];
        }
        __syncthreads();

        for (int t = 0; t < S; ++t) {
            // ---- phase 1: a = silu(hx @ W1h + b1h). split-K 4-way ---------
            {
                const int c = tid & 127, j4 = 4 * c, part = tid >> 7;   // 0..3
                ULL acc[8];
                if (part == 0) {
                    const ULL b01 = *(const ULL*)(b1h + j4);
                    const ULL b23 = *(const ULL*)(b1h + j4 + 2);
                    acc[0] = b01; acc[1] = swp(b01);
                    acc[2] = b23; acc[3] = swp(b23);
                    acc[4] = acc[0]; acc[5] = acc[1];
                    acc[6] = acc[2]; acc[7] = acc[3];
                } else {
                    #pragma unroll
                    for (int i = 0; i < 8; ++i) acc[i] = 0ULL;
                }
                dotp_mixed<80, WH>(acc, W1h + (size_t)(part * 80) * WH + j4,
                                   hxf + part * 80 * 8);
                if (part > 0) {
                    ULL* rp = rdA + ((size_t)(part - 1) * 128 + c) * 10;
                    #pragma unroll
                    for (int i = 0; i < 8; ++i) rp[i] = acc[i];
                }
                __syncthreads();
                if (part == 0) {
                    ULL v[8];
                    #pragma unroll
                    for (int i = 0; i < 8; ++i) v[i] = acc[i];
                    #pragma unroll
                    for (int p = 0; p < 3; ++p) {
                        const ULL* rp = rdA + ((size_t)p * 128 + c) * 10;
                        #pragma unroll
                        for (int i = 0; i < 8; ++i) v[i] = fadd2(v[i], rp[i]);
                    }
                    float y[M][4];
                    unscramble(v, y);
                    #pragma unroll
                    for (int jj = 0; jj < 4; ++jj) {
                        *(float4*)(a2f + (size_t)(j4 + jj) * 8) =
                            make_float4(silu_f(y[0][jj]), silu_f(y[1][jj]),
                                        silu_f(y[2][jj]), silu_f(y[3][jj]));
                    }
                }
            }
            __syncthreads();

            // ---- phase 2: h' = a @ W2h + b2h. split-K 8-way ---------------
            {
                const int c = tid & 63, j4 = 4 * c, q = tid >> 6;       // 0..7
                ULL acc[8];
                if (q == 0) {
                    const ULL b01 = *(const ULL*)(b2h + j4);
                    const ULL b23 = *(const ULL*)(b2h + j4 + 2);
                    acc[0] = b01; acc[1] = swp(b01);
                    acc[2] = b23; acc[3] = swp(b23);
                    acc[4] = acc[0]; acc[5] = acc[1];
                    acc[6] = acc[2]; acc[7] = acc[3];
                } else {
                    #pragma unroll
                    for (int i = 0; i < 8; ++i) acc[i] = 0ULL;
                }
                dotp_mixed<64, H>(acc, W2h + (size_t)(q * 64) * H + j4,
                                  a2f + q * 64 * 8);

                // prefetch x_{t+1} into regs (threads 256..511)
                float xv = 0.0f;
                int xm = 0, xd = 0;
                const bool xload = (tid >= 256) && (t + 1 < S);
                if (xload) {
                    xm = (tid - 256) & 3; xd = (tid - 256) >> 2;
                    xv = x[((size_t)(b0 + xm) * S + (t + 1)) * DIN + xd];
                }

                if (q > 0) {
                    ULL* rp = rdB + ((size_t)(q - 1) * 64 + c) * 10;
                    #pragma unroll
                    for (int i = 0; i < 8; ++i) rp[i] = acc[i];
                }
                __syncthreads();
                if (q == 0) {
                    ULL v[8];
                    #pragma unroll
                    for (int i = 0; i < 8; ++i) v[i] = acc[i];
                    #pragma unroll
                    for (int qi = 0; qi < 7; ++qi) {
                        const ULL* rp = rdB + ((size_t)qi * 64 + c) * 10;
                        #pragma unroll
                        for (int i = 0; i < 8; ++i) v[i] = fadd2(v[i], rp[i]);
                    }
                    float y[M][4];
                    unscramble(v, y);
                    // h' -> hx (batch-major) and hid (row-major)
                    #pragma unroll
                    for (int jj = 0; jj < 4; ++jj)
                        *(float4*)(hxf + (size_t)(j4 + jj) * 8) =
                            make_float4(y[0][jj], y[1][jj], y[2][jj], y[3][jj]);
                    #pragma unroll
                    for (int m = 0; m < M; ++m)
                        *(float4*)(hid + ((size_t)(t + 1) * B + (b0 + m)) * H + j4)
                            = make_float4(y[m][0], y[m][1], y[m][2], y[m][3]);
                }
                if (xload) hxf[(H + xd) * 8 + xm] = xv;   // x_{t+1} -> hx
            }
            __syncthreads();
            if (tid == 0) {
                __threadfence();                       // publish hid
                rel_store(&g_progress[bid], (unsigned)(t + 1));
            }
        }
    } else {
        // ========================= y branch (ymlp) ==========================
        const int i  = bid - REC_CTAS;
        const int t  = i >> 3;                // time step
        const int bt = i & 7;                 // batch tile
        const int b0 = bt * YROWS;

        // wait for the 8 recurrent CTAs covering rows [b0, b0+32)
        if (tid == 0) {
            const int c0 = b0 / M;
            const unsigned need = (unsigned)(t + 1);
            #pragma unroll
            for (int c = 0; c < YROWS / M; ++c) {
                while (acq_load(&g_progress[c0 + c]) < need) __nanosleep(256);
            }
        }
        __syncthreads();

        // load h rows (dup-packed) into smem
        ULL* hs = sm;             // [YROWS][H]
        ULL* us = sm + US_OFF;    // [YROWS][H]
        const float* hrow = hid + ((size_t)(t + 1) * B + b0) * H;
        for (int e = tid; e < YROWS * (H / 4); e += T) {
            const int r = e >> 6, c4 = (e & 63) * 4;
            const float4 v = *(const float4*)(hrow + (size_t)r * H + c4);
            ULL* dp = hs + r * H + c4;
            dp[0] = pack2(v.x, v.x); dp[1] = pack2(v.y, v.y);
            dp[2] = pack2(v.z, v.z); dp[3] = pack2(v.w, v.w);
        }
        __syncthreads();

        // GEMM1: u = silu(h @ W1y + b1y)   [32 x 256]
        {
            const int c = tid & 127, j2 = 2 * c, grp = tid >> 7, r0 = grp * 8;
            ULL acc[8];
            const ULL bias = *(const ULL*)(b1y + j2);
            #pragma unroll
            for (int r = 0; r < 8; ++r) acc[r] = bias;
            ydot<8, WY>(acc, W1y + j2, hs + r0 * H);
            #pragma unroll
            for (int r = 0; r < 8; ++r) {
                float z0, z1; unpack2(acc[r], z0, z1);
                const float s0 = silu_f(z0), s1 = silu_f(z1);
                ULL* up = us + (r0 + r) * H + j2;
                up[0] = pack2(s0, s0); up[1] = pack2(s1, s1);
            }
        }
        __syncthreads();

        // GEMM2: y = u @ W2y + b2y   [32 x 64] -> outs
        {
            const int cp = tid & 31, j2 = 2 * cp, g = tid >> 5, r0 = g * 2;
            ULL acc[2];
            const ULL bias = *(const ULL*)(b2y + j2);
            #pragma unroll
            for (int r = 0; r < 2; ++r) acc[r] = bias;
            ydot<2, DOUT>(acc, W2y + j2, us + r0 * H);
            #pragma unroll
            for (int r = 0; r < 2; ++r) {
                float y0, y1; unpack2(acc[r], y0, y1);
                *(float2*)(outs + ((size_t)(b0 + r0 + r) * S + t) * DOUT + j2)
                    = make_float2(y0, y1);
            }
        }
    }
}

extern "C" void kernel_launch(void* const* d_in, const int* in_sizes, int n_in,
                              void* d_out, int out_size) {
    (void)in_sizes; (void)n_in; (void)out_size;
    const float* x   = (const float*)d_in[0];
    const float* W1h = (const float*)d_in[1];
    const float* b1h = (const float*)d_in[2];
    const float* W2h = (const float*)d_in[3];
    const float* b2h = (const float*)d_in[4];
    const float* W1y = (const float*)d_in[5];
    const float* b1y = (const float*)d_in[6];
    const float* W2y = (const float*)d_in[7];
    const float* b2y = (const float*)d_in[8];

    float* outs = (float*)d_out;                       // [B, S, DOUT]
    float* hid  = outs + (size_t)B * S * DOUT;         // [S+1, B, H]

    cudaFuncSetAttribute(rnn_fused_kernel,
                         cudaFuncAttributeMaxDynamicSharedMemorySize,
                         DSMEM_BYTES);

    init_progress_kernel<<<1, 64>>>();
    rnn_fused_kernel<<<GRID, T, DSMEM_BYTES>>>(x, W1h, b1h, W2h, b2h,
                                               W1y, b1y, W2y, b2y, outs, hid);
}